// round 1
// baseline (speedup 1.0000x reference)
#include <cuda_runtime.h>
#include <cuda_bf16.h>

#define BB     16
#define SS     1024
#define HH     256
#define DMAX   4
#define TOUT   (SS * DMAX)          // 4096
#define NPITCH 256
#define NENERGY 256
#define H4     (HH / 4)             // 64 float4 per row

// frame -> source phoneme index; -1 = padding. 16*4096*4B = 256KB scratch.
__device__ int g_src[BB * TOUT];

// ---------------------------------------------------------------------------
// Kernel 1: per-batch duration round + inclusive scan + scatter src map.
// ---------------------------------------------------------------------------
__global__ void prep_kernel(const float* __restrict__ dur,
                            float* __restrict__ len_tail, int write_len)
{
    __shared__ int sc[SS];
    const int b = blockIdx.x;
    const int i = threadIdx.x;

    int d = __float2int_rn(dur[b * SS + i]);
    d = max(d, 0);
    sc[i] = d;

    // Hillis-Steele inclusive scan over 1024 elements
    #pragma unroll
    for (int off = 1; off < SS; off <<= 1) {
        __syncthreads();
        int v = (i >= off) ? sc[i - off] : 0;
        __syncthreads();
        sc[i] += v;
    }
    __syncthreads();

    const int csum = sc[i];
    const int len  = sc[SS - 1];

    // scatter: phoneme i owns frames [csum-d, csum)
    int* srcb = g_src + b * TOUT;
    for (int t = csum - d; t < csum; ++t)
        srcb[t] = i;

    // padding frames
    for (int t = len + i; t < TOUT; t += SS)
        srcb[t] = -1;

    if (write_len && i == 0)
        len_tail[b] = (float)len;
}

// ---------------------------------------------------------------------------
// quantize: replicate searchsorted(linspace(vmin,vmax,nb), v, side='left')
// ---------------------------------------------------------------------------
__device__ __forceinline__ int qbin(float v, float vmin, float vmax, int nb)
{
    v = fminf(fmaxf(v, vmin), vmax);
    const float step = (vmax - vmin) / (float)(nb - 1);
    float u = (v - vmin) / step;
    int i = (int)ceilf(u);
    i = min(max(i, 0), nb - 1);
    // fix-up: smallest i with (vmin + i*step) >= v
    while (i > 0 && (vmin + (float)(i - 1) * step) >= v) --i;
    while (i < nb - 1 && (vmin + (float)i * step) < v) ++i;
    return i;
}

// ---------------------------------------------------------------------------
// Kernel 2: expand + embed. 4 rows per 256-thread block; 64 lanes x float4.
// ---------------------------------------------------------------------------
__global__ void __launch_bounds__(256)
expand_kernel(const float4* __restrict__ enc,
              const float*  __restrict__ pitch_t,
              const float*  __restrict__ energy_t,
              const float4* __restrict__ ptab,
              const float4* __restrict__ etab,
              float4* __restrict__ out)
{
    const int row  = blockIdx.x * 4 + (threadIdx.x >> 6);   // 0..B*TOUT-1
    const int lane = threadIdx.x & 63;

    const int s = g_src[row];
    float4 r;
    if (s < 0) {
        r.x = r.y = r.z = r.w = 0.0f;
    } else {
        const int b  = row >> 12;                           // TOUT = 4096
        const int pb = qbin(pitch_t[row],  50.0f, 400.0f, NPITCH);
        const int eb = qbin(energy_t[row],  0.0f,   1.0f, NENERGY);

        float4 e = enc[(b * SS + s) * H4 + lane];
        float4 p = ptab[pb * H4 + lane];
        float4 q = etab[eb * H4 + lane];
        r.x = e.x + p.x + q.x;
        r.y = e.y + p.y + q.y;
        r.z = e.z + p.z + q.z;
        r.w = e.w + p.w + q.w;
    }
    out[row * H4 + lane] = r;
}

// ---------------------------------------------------------------------------
extern "C" void kernel_launch(void* const* d_in, const int* in_sizes, int n_in,
                              void* d_out, int out_size)
{
    const float* enc      = (const float*)d_in[0];  // [B,S,H]
    const float* pitch_t  = (const float*)d_in[1];  // [B,TOUT]
    const float* energy_t = (const float*)d_in[2];  // [B,TOUT]
    const float* dur      = (const float*)d_in[3];  // [B,S]
    const float* ptab     = (const float*)d_in[4];  // [NPITCH,H]
    const float* etab     = (const float*)d_in[5];  // [NENERGY,H]

    const long long main_elems = (long long)BB * TOUT * HH;
    const int write_len = (out_size > (int)main_elems) ? 1 : 0;
    float* len_tail = (float*)d_out + main_elems;

    prep_kernel<<<BB, SS>>>(dur, len_tail, write_len);

    const int nrows = BB * TOUT;                 // 65536
    expand_kernel<<<nrows / 4, 256>>>(
        (const float4*)enc, pitch_t, energy_t,
        (const float4*)ptab, (const float4*)etab,
        (float4*)d_out);
}

// round 3
// speedup vs baseline: 1.3742x; 1.3742x over previous
#include <cuda_runtime.h>
#include <cuda_bf16.h>

#define BB      16
#define SS      1024
#define HH      256
#define DMAX    4
#define TOUT    (SS * DMAX)          // 4096
#define NPITCH  256
#define NENERGY 256
#define H4      (HH / 4)             // 64 float4 per row

#define META_PAD 0xFFFFFFFFu

// frame -> source phoneme index; -1 = padding. 16*4096*4B = 256KB scratch.
__device__ int g_src[BB * TOUT];

// ---------------------------------------------------------------------------
// Kernel 1: per-batch duration round + inclusive scan + scatter src map.
// ---------------------------------------------------------------------------
__global__ void prep_kernel(const float* __restrict__ dur,
                            float* __restrict__ len_tail, int write_len)
{
    __shared__ int sc[SS];
    const int b = blockIdx.x;
    const int i = threadIdx.x;

    int d = __float2int_rn(dur[b * SS + i]);
    d = max(d, 0);
    sc[i] = d;

    #pragma unroll
    for (int off = 1; off < SS; off <<= 1) {
        __syncthreads();
        int v = (i >= off) ? sc[i - off] : 0;
        __syncthreads();
        sc[i] += v;
    }
    __syncthreads();

    const int csum = sc[i];
    const int len  = sc[SS - 1];

    int* srcb = g_src + b * TOUT;
    for (int t = csum - d; t < csum; ++t)
        srcb[t] = i;

    for (int t = len + i; t < TOUT; t += SS)
        srcb[t] = -1;

    if (write_len && i == 0)
        len_tail[b] = (float)len;
}

// ---------------------------------------------------------------------------
// quantize: replicate searchsorted(linspace(vmin,vmax,nb), v, side='left')
// ---------------------------------------------------------------------------
__device__ __forceinline__ int qbin(float v, float vmin, float vmax, int nb)
{
    v = fminf(fmaxf(v, vmin), vmax);
    const float step = (vmax - vmin) / (float)(nb - 1);
    float u = (v - vmin) / step;
    int i = (int)ceilf(u);
    i = min(max(i, 0), nb - 1);
    while (i > 0 && (vmin + (float)(i - 1) * step) >= v) --i;
    while (i < nb - 1 && (vmin + (float)i * step) < v) ++i;
    return i;
}

__device__ __forceinline__ float4 f4add3(float4 a, float4 b, float4 c)
{
    float4 r;
    r.x = a.x + b.x + c.x;
    r.y = a.y + b.y + c.y;
    r.z = a.z + b.z + c.z;
    r.w = a.w + b.w + c.w;
    return r;
}

// ---------------------------------------------------------------------------
// Kernel 2: expand + embed.
// One warp handles 2 rows; each lane handles float4 columns {lane, lane+32}
// of both rows => 12 independent gathers + 4 streaming stores per thread.
// Metadata (src, pbin, ebin) computed once per row by lanes 0/1, broadcast.
// ---------------------------------------------------------------------------
__global__ void __launch_bounds__(256)
expand_kernel(const float4* __restrict__ enc,
              const float*  __restrict__ pitch_t,
              const float*  __restrict__ energy_t,
              const float4* __restrict__ ptab,
              const float4* __restrict__ etab,
              float4* __restrict__ out)
{
    const int warp = blockIdx.x * 8 + (threadIdx.x >> 5);
    const int lane = threadIdx.x & 31;
    const int r0   = warp * 2;                  // rows r0, r0+1

    // lanes 0/1 compute packed meta for their row
    unsigned meta_l = META_PAD;
    if (lane < 2) {
        const int row = r0 + lane;
        const int s = g_src[row];
        if (s >= 0) {
            const int pb = qbin(pitch_t[row],  50.0f, 400.0f, NPITCH);
            const int eb = qbin(energy_t[row],  0.0f,   1.0f, NENERGY);
            meta_l = ((unsigned)s << 16) | ((unsigned)pb << 8) | (unsigned)eb;
        }
    }
    const unsigned m0 = __shfl_sync(0xFFFFFFFFu, meta_l, 0);
    const unsigned m1 = __shfl_sync(0xFFFFFFFFu, meta_l, 1);
    const int b = r0 >> 12;                     // TOUT = 4096; r0,r0+1 same batch

    const int j0 = lane;
    const int j1 = lane + 32;

    float4 o0a = {0.f,0.f,0.f,0.f}, o0b = o0a, o1a = o0a, o1b = o0a;

    if (m0 != META_PAD) {
        const float4* er = enc  + (((b * SS) + (int)(m0 >> 16)) << 6);
        const float4* pr = ptab + (((m0 >> 8) & 255u) << 6);
        const float4* qr = etab + ((m0 & 255u) << 6);
        float4 e0 = er[j0], e1 = er[j1];
        float4 p0 = pr[j0], p1 = pr[j1];
        float4 q0 = qr[j0], q1 = qr[j1];
        o0a = f4add3(e0, p0, q0);
        o0b = f4add3(e1, p1, q1);
    }
    if (m1 != META_PAD) {
        const float4* er = enc  + (((b * SS) + (int)(m1 >> 16)) << 6);
        const float4* pr = ptab + (((m1 >> 8) & 255u) << 6);
        const float4* qr = etab + ((m1 & 255u) << 6);
        float4 e0 = er[j0], e1 = er[j1];
        float4 p0 = pr[j0], p1 = pr[j1];
        float4 q0 = qr[j0], q1 = qr[j1];
        o1a = f4add3(e0, p0, q0);
        o1b = f4add3(e1, p1, q1);
    }

    // streaming stores: don't let the 64MB write stream evict enc/tables
    __stcs(&out[(long)r0 * H4 + j0],       o0a);
    __stcs(&out[(long)r0 * H4 + j1],       o0b);
    __stcs(&out[(long)(r0 + 1) * H4 + j0], o1a);
    __stcs(&out[(long)(r0 + 1) * H4 + j1], o1b);
}

// ---------------------------------------------------------------------------
extern "C" void kernel_launch(void* const* d_in, const int* in_sizes, int n_in,
                              void* d_out, int out_size)
{
    const float* enc      = (const float*)d_in[0];  // [B,S,H]
    const float* pitch_t  = (const float*)d_in[1];  // [B,TOUT]
    const float* energy_t = (const float*)d_in[2];  // [B,TOUT]
    const float* dur      = (const float*)d_in[3];  // [B,S]
    const float* ptab     = (const float*)d_in[4];  // [NPITCH,H]
    const float* etab     = (const float*)d_in[5];  // [NENERGY,H]

    const long long main_elems = (long long)BB * TOUT * HH;
    const int write_len = (out_size > (int)main_elems) ? 1 : 0;
    float* len_tail = (float*)d_out + main_elems;

    prep_kernel<<<BB, SS>>>(dur, len_tail, write_len);

    const int nrows = BB * TOUT;                 // 65536
    // 2 rows/warp, 8 warps/block => 16 rows/block => 4096 blocks
    expand_kernel<<<nrows / 16, 256>>>(
        (const float4*)enc, pitch_t, energy_t,
        (const float4*)ptab, (const float4*)etab,
        (float4*)d_out);
}

// round 4
// speedup vs baseline: 1.3956x; 1.0156x over previous
#include <cuda_runtime.h>
#include <cuda_bf16.h>

#define BB      16
#define SS      1024
#define HH      256
#define DMAX    4
#define TOUT    (SS * DMAX)          // 4096
#define NPITCH  256
#define NENERGY 256
#define H4      (HH / 4)             // 64 float4 per row

#define META_PAD 0xFFFFFFFFu

// frame -> source phoneme index; -1 = padding. 16*4096*4B = 256KB scratch.
__device__ int g_src[BB * TOUT];

// ---------------------------------------------------------------------------
// Kernel 1: per-batch duration round + warp-shuffle scan + scatter src map.
// ---------------------------------------------------------------------------
__global__ void prep_kernel(const float* __restrict__ dur,
                            float* __restrict__ len_tail, int write_len)
{
    __shared__ int wpre[33];            // wpre[w+1] = inclusive sum of warps 0..w
    const int b    = blockIdx.x;
    const int i    = threadIdx.x;
    const int wid  = i >> 5;
    const int lane = i & 31;

    int d = __float2int_rn(dur[b * SS + i]);
    d = max(d, 0);

    // intra-warp inclusive scan
    int x = d;
    #pragma unroll
    for (int off = 1; off < 32; off <<= 1) {
        int v = __shfl_up_sync(0xFFFFFFFFu, x, off);
        if (lane >= off) x += v;
    }
    if (lane == 31) wpre[wid + 1] = x;
    if (i == 0)     wpre[0] = 0;
    __syncthreads();

    // warp 0 scans the 32 warp sums
    if (wid == 0) {
        int v = wpre[lane + 1];
        #pragma unroll
        for (int off = 1; off < 32; off <<= 1) {
            int u = __shfl_up_sync(0xFFFFFFFFu, v, off);
            if (lane >= off) v += u;
        }
        wpre[lane + 1] = v;
    }
    __syncthreads();

    const int csum = x + wpre[wid];     // inclusive prefix over all 1024
    const int len  = wpre[32];

    int* srcb = g_src + b * TOUT;
    for (int t = csum - d; t < csum; ++t)
        srcb[t] = i;

    for (int t = len + i; t < TOUT; t += SS)
        srcb[t] = -1;

    if (write_len && i == 0)
        len_tail[b] = (float)len;
}

// ---------------------------------------------------------------------------
// quantize: replicate searchsorted(linspace(vmin,vmax,nb), v, side='left')
// ---------------------------------------------------------------------------
__device__ __forceinline__ int qbin(float v, float vmin, float vmax, int nb)
{
    v = fminf(fmaxf(v, vmin), vmax);
    const float step = (vmax - vmin) / (float)(nb - 1);
    float u = (v - vmin) / step;
    int i = (int)ceilf(u);
    i = min(max(i, 0), nb - 1);
    while (i > 0 && (vmin + (float)(i - 1) * step) >= v) --i;
    while (i < nb - 1 && (vmin + (float)i * step) < v) ++i;
    return i;
}

__device__ __forceinline__ float4 f4add3(float4 a, float4 b, float4 c)
{
    float4 r;
    r.x = a.x + b.x + c.x;
    r.y = a.y + b.y + c.y;
    r.z = a.z + b.z + c.z;
    r.w = a.w + b.w + c.w;
    return r;
}

// ---------------------------------------------------------------------------
// Kernel 2: expand + embed.
// One warp handles 4 consecutive rows; each lane handles float4 columns
// {lane, lane+32}. Meta for the 4 rows computed by lanes 0-3, broadcast.
// Consecutive rows often share the same src phoneme (avg duration 2.5):
// dedup the enc row load via warp-uniform cur_s check.
// ---------------------------------------------------------------------------
__global__ void __launch_bounds__(256)
expand_kernel(const float4* __restrict__ enc,
              const float*  __restrict__ pitch_t,
              const float*  __restrict__ energy_t,
              const float4* __restrict__ ptab,
              const float4* __restrict__ etab,
              float4* __restrict__ out)
{
    const int warp = blockIdx.x * 8 + (threadIdx.x >> 5);
    const int lane = threadIdx.x & 31;
    const int r0   = warp * 4;                 // rows r0..r0+3, same batch

    unsigned meta_l = META_PAD;
    if (lane < 4) {
        const int row = r0 + lane;
        const int s = g_src[row];
        if (s >= 0) {
            const int pb = qbin(pitch_t[row],  50.0f, 400.0f, NPITCH);
            const int eb = qbin(energy_t[row],  0.0f,   1.0f, NENERGY);
            meta_l = ((unsigned)s << 16) | ((unsigned)pb << 8) | (unsigned)eb;
        }
    }
    unsigned m[4];
    m[0] = __shfl_sync(0xFFFFFFFFu, meta_l, 0);
    m[1] = __shfl_sync(0xFFFFFFFFu, meta_l, 1);
    m[2] = __shfl_sync(0xFFFFFFFFu, meta_l, 2);
    m[3] = __shfl_sync(0xFFFFFFFFu, meta_l, 3);

    const int b  = r0 >> 12;                   // TOUT = 4096
    const int j0 = lane;
    const int j1 = lane + 32;

    float4 e0, e1;
    int cur_s = -1;

    #pragma unroll
    for (int k = 0; k < 4; ++k) {
        float4 oa = {0.f, 0.f, 0.f, 0.f}, ob = oa;
        const unsigned mk = m[k];
        if (mk != META_PAD) {
            const int s = (int)(mk >> 16);
            if (s != cur_s) {                  // warp-uniform branch
                const float4* er = enc + (((b * SS) + s) << 6);
                e0 = er[j0];
                e1 = er[j1];
                cur_s = s;
            }
            const float4* pr = ptab + (((mk >> 8) & 255u) << 6);
            const float4* qr = etab + ((mk & 255u) << 6);
            float4 p0 = pr[j0], p1 = pr[j1];
            float4 q0 = qr[j0], q1 = qr[j1];
            oa = f4add3(e0, p0, q0);
            ob = f4add3(e1, p1, q1);
        }
        __stcs(&out[(long)(r0 + k) * H4 + j0], oa);
        __stcs(&out[(long)(r0 + k) * H4 + j1], ob);
    }
}

// ---------------------------------------------------------------------------
extern "C" void kernel_launch(void* const* d_in, const int* in_sizes, int n_in,
                              void* d_out, int out_size)
{
    const float* enc      = (const float*)d_in[0];  // [B,S,H]
    const float* pitch_t  = (const float*)d_in[1];  // [B,TOUT]
    const float* energy_t = (const float*)d_in[2];  // [B,TOUT]
    const float* dur      = (const float*)d_in[3];  // [B,S]
    const float* ptab     = (const float*)d_in[4];  // [NPITCH,H]
    const float* etab     = (const float*)d_in[5];  // [NENERGY,H]

    const long long main_elems = (long long)BB * TOUT * HH;
    const int write_len = (out_size > (int)main_elems) ? 1 : 0;
    float* len_tail = (float*)d_out + main_elems;

    prep_kernel<<<BB, SS>>>(dur, len_tail, write_len);

    const int nrows = BB * TOUT;                 // 65536
    // 4 rows/warp, 8 warps/block => 32 rows/block => 2048 blocks
    expand_kernel<<<nrows / 32, 256>>>(
        (const float4*)enc, pitch_t, energy_t,
        (const float4*)ptab, (const float4*)etab,
        (float4*)d_out);
}